// round 4
// baseline (speedup 1.0000x reference)
#include <cuda_runtime.h>

#define N_EQ    131072
#define NTILES  8704            // 139264 / 16 points per tile
#define TILE_EQ 8192
#define TILE_IB 8448
#define NU      0.0031830988618379067154f

typedef unsigned long long u64;

__device__ __forceinline__ u64 pk2(float lo, float hi) {
    u64 r; asm("mov.b64 %0, {%1, %2};" : "=l"(r) : "f"(lo), "f"(hi)); return r;
}
__device__ __forceinline__ void upk2(u64 v, float& lo, float& hi) {
    asm("mov.b64 {%0, %1}, %2;" : "=f"(lo), "=f"(hi) : "l"(v));
}
__device__ __forceinline__ void fma2(u64& d, u64 a, u64 b) {
    asm("fma.rn.f32x2 %0, %1, %2, %0;" : "+l"(d) : "l"(a), "l"(b));
}
__device__ __forceinline__ u64 add2(u64 a, u64 b) {
    u64 r; asm("add.rn.f32x2 %0, %1, %2;" : "=l"(r) : "l"(a), "l"(b)); return r;
}
__device__ __forceinline__ float hadd2(u64 v) {
    float lo, hi; upk2(v, lo, hi); return lo + hi;
}
__device__ __forceinline__ float tanhf_fast(float z) {
    float e = __expf(2.0f * z);
    return __fdividef(e - 1.0f, e + 1.0f);
}

// Shared memory (bytes):
//   sWk : 3 layers x 64 kp x 128 j u64          = 196608 @ 0
//   st  : 16 pt x 262 u64 (256 used + 6 pad)    =  33536 @ 196608
//   sW4 : 64 u64                                 =    512 @ 230144
// total = 230656  (<= ~232448 limit)
#define ST_STRIDE 262
#define SMEM_BYTES 230656

extern __shared__ char smem_raw[];

__global__ __launch_bounds__(512, 1)
void pinn_kernel(const float* __restrict__ tx_eq,
                 const float* __restrict__ tx_init,
                 const float* __restrict__ tx_bnd,
                 const float* __restrict__ W0, const float* __restrict__ b0,
                 const float* __restrict__ W1, const float* __restrict__ b1,
                 const float* __restrict__ W2, const float* __restrict__ b2,
                 const float* __restrict__ W3, const float* __restrict__ b3,
                 const float* __restrict__ W4, const float* __restrict__ b4,
                 float* __restrict__ out)
{
    u64* sWk = (u64*)smem_raw;                    // [l][kp][j]
    u64* stU = (u64*)(smem_raw + 196608);         // [pt][ST_STRIDE]
    u64* sW4 = (u64*)(smem_raw + 230144);         // [kp]

    const int tid  = threadIdx.x;
    const int lane = tid & 31;
    const int w    = tid >> 5;        // 0..15
    const int Wj   = w & 3;           // j-group of warp
    const int Wc   = w >> 2;          // pt-group of warp
    const int jg   = lane >> 2;       // 0..7
    const int cg   = lane & 3;        // 0..3
    const int jb   = Wj * 32 + jg * 4;    // thread's 4 neurons jb..jb+3
    const int pt   = Wc * 4 + cg;          // thread's point 0..15

    // ---- Build k-pair-interleaved weights in smem (once; persistent) ----
    {
        const float* Wsrc[3] = { W1, W2, W3 };
        #pragma unroll
        for (int l = 0; l < 3; l++) {
            const float* Wm = Wsrc[l];
            for (int i = tid; i < 8192; i += 512) {
                const int kp = i >> 7, j = i & 127;
                sWk[l * 8192 + i] = pk2(Wm[(2*kp) * 128 + j], Wm[(2*kp+1) * 128 + j]);
            }
        }
        if (tid < 64) sW4[tid] = pk2(W4[2*tid], W4[2*tid+1]);
    }

    // Layer-0 params for this thread's fixed kp0 = tid & 63 (j = 2kp0, 2kp0+1)
    const int k0 = tid & 63;
    const float l0t0 = __ldg(W0 + 2*k0),       l0t1 = __ldg(W0 + 2*k0 + 1);
    const float l0x0 = __ldg(W0 + 128 + 2*k0), l0x1 = __ldg(W0 + 128 + 2*k0 + 1);
    const float l0b0 = __ldg(b0 + 2*k0),       l0b1 = __ldg(b0 + 2*k0 + 1);
    // Biases for layers 1..3, this thread's 4 neurons
    float bl[3][4];
    #pragma unroll
    for (int n = 0; n < 4; n++) {
        bl[0][n] = __ldg(b1 + jb + n);
        bl[1][n] = __ldg(b2 + jb + n);
        bl[2][n] = __ldg(b3 + jb + n);
    }
    const float b4s = __ldg(b4);
    __syncthreads();

    for (int tile = blockIdx.x; tile < NTILES; tile += gridDim.x) {
        const float2* src;
        if (tile < TILE_EQ)      src = (const float2*)tx_eq  + tile * 16;
        else if (tile < TILE_IB) src = (const float2*)tx_init + (tile - TILE_EQ) * 16;
        else                     src = (const float2*)tx_bnd  + (tile - TILE_IB) * 16;

        // ---- Layer 0: 2 -> 128, tanh; thread handles (pt0,k0) and (pt0+8,k0) ----
        {
            const int pt0 = tid >> 6;   // 0..7
            #pragma unroll
            for (int it = 0; it < 2; it++) {
                const int p = pt0 + 8 * it;
                const float2 t = __ldg(src + p);
                float a[2], at[2], ax[2], axx[2];
                #pragma unroll
                for (int m = 0; m < 2; m++) {
                    const float wt = m ? l0t1 : l0t0;
                    const float wx = m ? l0x1 : l0x0;
                    const float bb = m ? l0b1 : l0b0;
                    const float z  = fmaf(wt, t.x, fmaf(wx, t.y, bb));
                    const float av = tanhf_fast(z);
                    const float ap = 1.0f - av * av;
                    a[m] = av; at[m] = ap * wt; ax[m] = ap * wx;
                    axx[m] = -2.0f * av * ax[m] * wx;
                }
                u64* d = stU + p * ST_STRIDE + k0 * 4;
                ((ulonglong2*)d)[0] = make_ulonglong2(pk2(a[0], a[1]),  pk2(at[0],  at[1]));
                ((ulonglong2*)d)[1] = make_ulonglong2(pk2(ax[0], ax[1]), pk2(axx[0], axx[1]));
            }
        }
        __syncthreads();

        // ---- Layers 1..3: 128 -> 128, k-pair packed forward-mode AD ----
        #pragma unroll
        for (int l = 0; l < 3; l++) {
            const u64* Wb = sWk + l * 8192 + jb;
            const u64* sp = stU + pt * ST_STRIDE;

            u64 acc[4][4];   // [state][neuron]
            #pragma unroll
            for (int s = 0; s < 4; s++)
                #pragma unroll
                for (int n = 0; n < 4; n++) acc[s][n] = 0ull;

            #pragma unroll 8
            for (int kp = 0; kp < 64; kp++) {
                const ulonglong2 w01 = *(const ulonglong2*)(Wb + kp * 128);
                const ulonglong2 w23 = *(const ulonglong2*)(Wb + kp * 128 + 2);
                const ulonglong2 sa  = *(const ulonglong2*)(sp + kp * 4);      // (a,t)
                const ulonglong2 sb  = *(const ulonglong2*)(sp + kp * 4 + 2);  // (x,xx)

                fma2(acc[0][0], w01.x, sa.x); fma2(acc[0][1], w01.y, sa.x);
                fma2(acc[0][2], w23.x, sa.x); fma2(acc[0][3], w23.y, sa.x);
                fma2(acc[1][0], w01.x, sa.y); fma2(acc[1][1], w01.y, sa.y);
                fma2(acc[1][2], w23.x, sa.y); fma2(acc[1][3], w23.y, sa.y);
                fma2(acc[2][0], w01.x, sb.x); fma2(acc[2][1], w01.y, sb.x);
                fma2(acc[2][2], w23.x, sb.x); fma2(acc[2][3], w23.y, sb.x);
                fma2(acc[3][0], w01.x, sb.y); fma2(acc[3][1], w01.y, sb.y);
                fma2(acc[3][2], w23.x, sb.y); fma2(acc[3][3], w23.y, sb.y);
            }
            __syncthreads();   // all reads of this layer done before rewrites

            float a[4], at[4], ax[4], axx[4];
            #pragma unroll
            for (int n = 0; n < 4; n++) {
                const float z   = hadd2(acc[0][n]) + bl[l][n];
                const float zt  = hadd2(acc[1][n]);
                const float zx  = hadd2(acc[2][n]);
                const float zxx = hadd2(acc[3][n]);
                const float av  = tanhf_fast(z);
                const float ap  = 1.0f - av * av;
                a[n]  = av;
                at[n] = ap * zt;
                ax[n] = ap * zx;
                axx[n] = fmaf(-2.0f * av * ax[n], zx, ap * zxx);
            }
            {
                const int kp0 = jb >> 1;
                u64* d0 = stU + pt * ST_STRIDE + kp0 * 4;
                ((ulonglong2*)d0)[0] = make_ulonglong2(pk2(a[0], a[1]),  pk2(at[0],  at[1]));
                ((ulonglong2*)d0)[1] = make_ulonglong2(pk2(ax[0], ax[1]), pk2(axx[0], axx[1]));
                u64* d1 = d0 + 4;
                ((ulonglong2*)d1)[0] = make_ulonglong2(pk2(a[2], a[3]),  pk2(at[2],  at[3]));
                ((ulonglong2*)d1)[1] = make_ulonglong2(pk2(ax[2], ax[3]), pk2(axx[2], axx[3]));
            }
            __syncthreads();
        }

        // ---- Layer 4: 128 -> 1 linear; warp w reduces point pt=w ----
        {
            u64 r0 = 0ull, r1 = 0ull, r2 = 0ull, r3 = 0ull;
            const u64* sp = stU + w * ST_STRIDE;
            #pragma unroll
            for (int m = 0; m < 2; m++) {
                const int kp = lane + 32 * m;
                const u64 wv = sW4[kp];
                const ulonglong2 sa = *(const ulonglong2*)(sp + kp * 4);
                const ulonglong2 sb = *(const ulonglong2*)(sp + kp * 4 + 2);
                fma2(r0, wv, sa.x);
                fma2(r1, wv, sa.y);
                fma2(r2, wv, sb.x);
                fma2(r3, wv, sb.y);
            }
            #pragma unroll
            for (int off = 16; off > 0; off >>= 1) {
                r0 = add2(r0, __shfl_down_sync(0xffffffffu, r0, off));
                r1 = add2(r1, __shfl_down_sync(0xffffffffu, r1, off));
                r2 = add2(r2, __shfl_down_sync(0xffffffffu, r2, off));
                r3 = add2(r3, __shfl_down_sync(0xffffffffu, r3, off));
            }
            if (lane == 0) {
                const float u   = hadd2(r0) + b4s;
                const float ut  = hadd2(r1);
                const float ux  = hadd2(r2);
                const float uxx = hadd2(r3);
                out[tile * 16 + w] = (tile < TILE_EQ) ? (fmaf(u, ux, ut) - NU * uxx) : u;
            }
        }
        __syncthreads();   // layer-4 reads done before next tile's layer-0 stores
    }
}

extern "C" void kernel_launch(void* const* d_in, const int* in_sizes, int n_in,
                              void* d_out, int out_size)
{
    const float* tx_eq   = (const float*)d_in[0];
    const float* tx_init = (const float*)d_in[1];
    const float* tx_bnd  = (const float*)d_in[2];
    const float* W0 = (const float*)d_in[3];
    const float* b0 = (const float*)d_in[4];
    const float* W1 = (const float*)d_in[5];
    const float* b1 = (const float*)d_in[6];
    const float* W2 = (const float*)d_in[7];
    const float* b2 = (const float*)d_in[8];
    const float* W3 = (const float*)d_in[9];
    const float* b3 = (const float*)d_in[10];
    const float* W4 = (const float*)d_in[11];
    const float* b4 = (const float*)d_in[12];
    float* out = (float*)d_out;

    cudaFuncSetAttribute(pinn_kernel,
                         cudaFuncAttributeMaxDynamicSharedMemorySize,
                         SMEM_BYTES);

    int sms = 148;
    cudaDeviceGetAttribute(&sms, cudaDevAttrMultiProcessorCount, 0);
    if (sms > NTILES) sms = NTILES;

    pinn_kernel<<<sms, 512, SMEM_BYTES>>>(
        tx_eq, tx_init, tx_bnd,
        W0, b0, W1, b1, W2, b2, W3, b3, W4, b4,
        out);
}